// round 10
// baseline (speedup 1.0000x reference)
#include <cuda_runtime.h>
#include <cuda_fp16.h>
#include <cstdint>
#include <cstddef>

#define N_ROWS 8192
#define D_IN   4096
#define D_OUT  4096
#define T_TASK 10
#define RANK_  16
#define K_LORA 160
#define SCALING (1.0f/16.0f)

// ---------- device scratch (static: no runtime allocation) ----------
__device__ __align__(256) __half g_xh[(size_t)N_ROWS*D_IN];
__device__ __align__(256) __half g_wh[(size_t)D_OUT*D_IN];
__device__ __align__(256) __half g_ahT[(size_t)D_IN*K_LORA];   // AhT[i][k] = Acat[k][i]
__device__ __align__(256) __half g_bh [(size_t)D_OUT*K_LORA];  // Bh[o][k]  = Bcat[o][k]
__device__ int g_convCnt[32];   // per 256-row m-block of x, target 16
__device__ int g_foldCnt[16];   // per 256-row o-block of W_eff, target 32

// ---------- helpers ----------
__device__ __forceinline__ uint32_t smem_u32(const void* p){
    return (uint32_t)__cvta_generic_to_shared(p);
}
__device__ __forceinline__ void cp16(uint32_t dst, const void* src){
    asm volatile("cp.async.cg.shared.global [%0], [%1], 16;" :: "r"(dst), "l"(src) : "memory");
}

#define LDSM4(r0,r1,r2,r3,addr) \
    asm volatile("ldmatrix.sync.aligned.m8n8.x4.shared.b16 {%0,%1,%2,%3}, [%4];" \
                 : "=r"(r0), "=r"(r1), "=r"(r2), "=r"(r3) : "r"(addr))

#define MMA16816(c,a,b) \
    asm volatile("mma.sync.aligned.m16n8k16.row.col.f32.f16.f16.f32 " \
                 "{%0,%1,%2,%3}, {%4,%5,%6,%7}, {%8,%9}, {%0,%1,%2,%3};" \
                 : "+f"((c)[0]), "+f"((c)[1]), "+f"((c)[2]), "+f"((c)[3]) \
                 : "r"((a)[0]), "r"((a)[1]), "r"((a)[2]), "r"((a)[3]), \
                   "r"((b)[0]), "r"((b)[1]))

// ---------- kernel P1: zero flags + convert lA (transposed) and lB to fp16 ----------
__global__ void __launch_bounds__(256) prep_kernel(const float* __restrict__ lA,
                                                   const float* __restrict__ lB){
    const size_t TOT = (size_t)D_IN * K_LORA;   // 655360
    size_t gid = (size_t)blockIdx.x*256u + threadIdx.x;
    if (gid < 32) g_convCnt[gid] = 0;
    else if (gid < 48) g_foldCnt[gid-32] = 0;
    if (gid < TOT){
        int i = (int)(gid / K_LORA), k = (int)(gid % K_LORA);
        g_ahT[gid] = __float2half(lA[(size_t)k*D_IN + i]);   // lA [T,R,D_IN] flat
    } else if (gid < 2*TOT){
        size_t g = gid - TOT;
        int o = (int)(g / K_LORA), k = (int)(g % K_LORA);
        int t = k >> 4, r = k & 15;
        g_bh[g] = __float2half(lB[(size_t)t*D_OUT*RANK_ + (size_t)o*RANK_ + r]);
    }
}

// ---------- merged kernel: conv [0,512) | fold [512,1024) | gemm [1024,2048) ----------
// GEMM: CTA tile 256(M) x 128(N), 16 warps (4x4), warp tile 64x32, K=4096 in 64-chunks,
//       4-stage cp.async ring, one __syncthreads per chunk, 144B padded rows.
// Fold: CTA tile 256(o) x 128(i), K=160 fp16 mma, 336B padded rows,
//       epilogue W_eff = fp16(W + acc/16) -> g_wh, then flag.
#define MT 256
#define NT 128
#define SROW 144
#define A_ST (MT*SROW)                 // 36864
#define B_ST (NT*SROW)                 // 18432
#define STG  (A_ST + B_ST)             // 55296
#define NSTAGE 4
#define GEMM_SMEM (NSTAGE*STG)         // 221184
#define NKI 64
#define FROW 336
#define FA_ST (256*FROW)               // 86016

__global__ void __launch_bounds__(512, 1)
fused_kernel(const float* __restrict__ W, const float* __restrict__ x,
             const float* __restrict__ bias, float* __restrict__ out){
    extern __shared__ char smem[];
    const uint32_t sbase = smem_u32(smem);
    const int bid = blockIdx.x;
    const int tid = threadIdx.x;
    const int wid = tid >> 5;
    const int l   = tid & 31;

    if (bid < 512){
        // ---------------- x -> fp16 conversion: rows [bid*16, bid*16+16) ----------------
        const size_t base = (size_t)bid * 16 * D_IN;
        const float4* src = reinterpret_cast<const float4*>(x + base);
#pragma unroll 4
        for (int it = 0; it < 32; it++){
            size_t i4 = (size_t)it*512 + tid;
            float4 v = src[i4];
            __half h[4];
            h[0]=__float2half(v.x); h[1]=__float2half(v.y);
            h[2]=__float2half(v.z); h[3]=__float2half(v.w);
            *reinterpret_cast<uint2*>(g_xh + base + i4*4) = *reinterpret_cast<uint2*>(h);
        }
        __threadfence();
        __syncthreads();
        if (tid == 0) atomicAdd(&g_convCnt[bid >> 4], 1);
        return;
    }

    if (bid < 1024){
        // ---------------- fold tile: o0 = ot*256, i0 = it*128, K=160 ----------------
        const int fbid = bid - 512;
        const int ot = fbid >> 5;            // 0..15
        const int o0 = ot * 256;
        const int i0 = (fbid & 31) * 128;
        const uint32_t sa = sbase;           // Bh tile: 256 rows x 336B (320B valid)
        const uint32_t sb = sbase + FA_ST;   // AhT tile: 128 rows x 336B (320B valid)
        {
            // A-tile: 256 rows x 320B; 2 thr/row, each 160B = 10 x 16B chunks
            const int rA = tid >> 1, hA = tid & 1;
            const __half* gA = g_bh + (size_t)(o0 + rA)*K_LORA + hA*80;
            const uint32_t da = sa + (uint32_t)rA*FROW + (uint32_t)hA*160;
#pragma unroll
            for (int c=0;c<10;c++) cp16(da + c*16, gA + c*8);
            // B-tile: 128 rows x 320B; 4 thr/row, each 80B = 5 x 16B chunks
            const int rB = tid >> 2, qB = tid & 3;
            const __half* gB = g_ahT + (size_t)(i0 + rB)*K_LORA + qB*40;
            const uint32_t db = sb + (uint32_t)rB*FROW + (uint32_t)qB*80;
#pragma unroll
            for (int c=0;c<5;c++) cp16(db + c*16, gB + c*8);
        }
        asm volatile("cp.async.commit_group;\n\tcp.async.wait_group 0;" ::: "memory");
        __syncthreads();

        const int wm = wid & 3;     // o-group of 64
        const int wn = wid >> 2;    // i-group of 32
        float acc[4][4][4];
#pragma unroll
        for (int mi=0;mi<4;mi++)
#pragma unroll
            for (int nj=0;nj<4;nj++)
#pragma unroll
                for (int e=0;e<4;e++) acc[mi][nj][e] = 0.f;

        const uint32_t a_lane = (uint32_t)(wm*64 + (l & 15)) * FROW + (uint32_t)((l >> 4) & 1) * 16;
        const uint32_t b_lane = (uint32_t)(wn*32 + (l & 7) + ((l >> 4) & 1)*8) * FROW
                              + (uint32_t)((l >> 3) & 1) * 16;
#pragma unroll
        for (int ks = 0; ks < 10; ks++){
            uint32_t a[4][4];
#pragma unroll
            for (int mi=0;mi<4;mi++){
                uint32_t addr = sa + a_lane + (uint32_t)(mi*16)*FROW + (uint32_t)ks*32;
                LDSM4(a[mi][0], a[mi][1], a[mi][2], a[mi][3], addr);
            }
            uint32_t b[4][2];
#pragma unroll
            for (int nb=0;nb<2;nb++){
                uint32_t addr = sb + b_lane + (uint32_t)(nb*16)*FROW + (uint32_t)ks*32;
                LDSM4(b[2*nb][0], b[2*nb][1], b[2*nb+1][0], b[2*nb+1][1], addr);
            }
#pragma unroll
            for (int mi=0;mi<4;mi++)
#pragma unroll
                for (int nj=0;nj<4;nj++)
                    MMA16816(acc[mi][nj], a[mi], b[nj]);
        }

#pragma unroll
        for (int mi=0;mi<4;mi++){
            const int m = o0 + wm*64 + mi*16 + (l >> 2);
#pragma unroll
            for (int nj=0;nj<4;nj++){
                const int n = i0 + wn*32 + nj*8 + (l & 3)*2;
                float2 w01 = *reinterpret_cast<const float2*>(W + (size_t)m*D_IN + n);
                float2 w23 = *reinterpret_cast<const float2*>(W + (size_t)(m+8)*D_IN + n);
                __half2 h0 = __floats2half2_rn(w01.x + acc[mi][nj][0]*SCALING,
                                               w01.y + acc[mi][nj][1]*SCALING);
                __half2 h1 = __floats2half2_rn(w23.x + acc[mi][nj][2]*SCALING,
                                               w23.y + acc[mi][nj][3]*SCALING);
                *reinterpret_cast<__half2*>(g_wh + (size_t)m*D_IN + n)     = h0;
                *reinterpret_cast<__half2*>(g_wh + (size_t)(m+8)*D_IN + n) = h1;
            }
        }
        __threadfence();
        __syncthreads();
        if (tid == 0) atomicAdd(&g_foldCnt[ot], 1);
        return;
    }

    // ---------------- GEMM CTA: m-fastest raster ----------------
    const int gb  = bid - 1024;
    const int m_t = gb & 31;
    const int n_t = gb >> 5;
    const int m0  = m_t * MT;
    const int n0  = n_t * NT;

    // wait for producers (own tiles only)
    if (tid == 0){
        while (atomicAdd(&g_foldCnt[n_t >> 1], 0) < 32) { }
        while (atomicAdd(&g_convCnt[m_t], 0) < 16) { }
        __threadfence();
    }
    __syncthreads();

    const int wm  = wid & 3;    // 4 M-groups of 64
    const int wn  = wid >> 2;   // 4 N-groups of 32

    float acc[4][4][4];
#pragma unroll
    for (int mi=0;mi<4;mi++)
#pragma unroll
        for (int nj=0;nj<4;nj++)
#pragma unroll
            for (int e=0;e<4;e++) acc[mi][nj][e] = 0.f;

    const int arow = tid >> 1, ah = tid & 1;       // A: 256 rows, 2 thr/row, 4x16B
    const int brow = tid >> 2, bq = tid & 3;       // B: 128 rows, 4 thr/row, 2x16B

    auto issue_load = [&](int kk){
        const int k0  = kk << 6;
        const uint32_t as = sbase + (uint32_t)(kk % NSTAGE) * STG;
        const uint32_t bs = as + A_ST;
        const __half* ga = g_xh + (size_t)(m0 + arow)*D_IN + k0 + ah*32;
        const uint32_t adst = as + (uint32_t)arow*SROW + (uint32_t)ah*64;
#pragma unroll
        for (int c=0;c<4;c++) cp16(adst + c*16, ga + c*8);
        const __half* gbp = g_wh + (size_t)(n0 + brow)*D_IN + k0 + bq*16;
        const uint32_t bdst = bs + (uint32_t)brow*SROW + (uint32_t)bq*32;
#pragma unroll
        for (int c=0;c<2;c++) cp16(bdst + c*16, gbp + c*8);
        asm volatile("cp.async.commit_group;" ::: "memory");
    };

    issue_load(0);
    issue_load(1);
    issue_load(2);

    const uint32_t a_lane = (uint32_t)(wm*64 + (l & 15)) * SROW + (uint32_t)((l >> 4) & 1) * 16;
    const uint32_t b_lane = (uint32_t)(wn*32 + (l & 7) + ((l >> 4) & 1)*8) * SROW
                          + (uint32_t)((l >> 3) & 1) * 16;

    for (int kk = 0; kk < NKI; kk++){
        asm volatile("cp.async.wait_group 2;" ::: "memory");
        __syncthreads();

        if (kk + 3 < NKI) issue_load(kk + 3);
        else asm volatile("cp.async.commit_group;" ::: "memory");

        const uint32_t as = sbase + (uint32_t)(kk % NSTAGE) * STG;
        const uint32_t bs = as + A_ST;

#pragma unroll
        for (int ks = 0; ks < 4; ks++){
            uint32_t a[4][4];
#pragma unroll
            for (int mi=0;mi<4;mi++){
                uint32_t addr = as + a_lane + (uint32_t)(mi*16)*SROW + (uint32_t)ks*32;
                LDSM4(a[mi][0], a[mi][1], a[mi][2], a[mi][3], addr);
            }
            uint32_t b[4][2];
#pragma unroll
            for (int nb=0;nb<2;nb++){
                uint32_t addr = bs + b_lane + (uint32_t)(nb*16)*SROW + (uint32_t)ks*32;
                LDSM4(b[2*nb][0], b[2*nb][1], b[2*nb+1][0], b[2*nb+1][1], addr);
            }
#pragma unroll
            for (int mi=0;mi<4;mi++)
#pragma unroll
                for (int nj=0;nj<4;nj++)
                    MMA16816(acc[mi][nj], a[mi], b[nj]);
        }
    }

    // epilogue: add bias, store fp32
#pragma unroll
    for (int mi=0;mi<4;mi++){
        const int m = m0 + wm*64 + mi*16 + (l >> 2);
#pragma unroll
        for (int nj=0;nj<4;nj++){
            const int n = n0 + wn*32 + nj*8 + (l & 3)*2;
            const float b0 = bias[n], b1 = bias[n+1];
            float2 v0 = make_float2(acc[mi][nj][0] + b0, acc[mi][nj][1] + b1);
            float2 v1 = make_float2(acc[mi][nj][2] + b0, acc[mi][nj][3] + b1);
            *reinterpret_cast<float2*>(out + (size_t)m*D_OUT + n)       = v0;
            *reinterpret_cast<float2*>(out + (size_t)(m+8)*D_OUT + n)   = v1;
        }
    }
}

// ---------- launch ----------
extern "C" void kernel_launch(void* const* d_in, const int* in_sizes, int n_in,
                              void* d_out, int out_size){
    const float* x  = (const float*)d_in[0];
    const float* W  = (const float*)d_in[1];
    const float* b  = (const float*)d_in[2];
    const float* lA = (const float*)d_in[3];
    const float* lB = (const float*)d_in[4];
    float* out = (float*)d_out;

    cudaFuncSetAttribute(fused_kernel,
                         cudaFuncAttributeMaxDynamicSharedMemorySize, GEMM_SMEM);

    prep_kernel<<<(2*(size_t)D_IN*K_LORA + 255)/256, 256>>>(lA, lB);
    fused_kernel<<<2048, 512, GEMM_SMEM>>>(W, x, b, out);
}

// round 11
// speedup vs baseline: 1.0147x; 1.0147x over previous
#include <cuda_runtime.h>
#include <cuda_fp16.h>
#include <cstdint>
#include <cstddef>

#define N_ROWS 8192
#define D_IN   4096
#define D_OUT  4096
#define T_TASK 10
#define RANK_  16
#define K_LORA 160
#define SCALING (1.0f/16.0f)

// ---------- device scratch (static: no runtime allocation) ----------
__device__ __align__(256) __half g_xh[(size_t)N_ROWS*D_IN];
__device__ __align__(256) __half g_wh[(size_t)D_OUT*D_IN];
__device__ __align__(256) __half g_ahT[(size_t)D_IN*K_LORA];   // AhT[i][k] = Acat[k][i]
__device__ __align__(256) __half g_bh [(size_t)D_OUT*K_LORA];  // Bh[o][k]  = Bcat[o][k]
__device__ int g_convCnt[32];   // per 256-row m-block of x, target 16
__device__ int g_foldCnt[16];   // per 256-row o-block of W_eff, target 32

// ---------- helpers ----------
__device__ __forceinline__ uint32_t smem_u32(const void* p){
    return (uint32_t)__cvta_generic_to_shared(p);
}
__device__ __forceinline__ void cp16(uint32_t dst, const void* src){
    asm volatile("cp.async.cg.shared.global [%0], [%1], 16;" :: "r"(dst), "l"(src) : "memory");
}

#define LDSM4(r0,r1,r2,r3,addr) \
    asm volatile("ldmatrix.sync.aligned.m8n8.x4.shared.b16 {%0,%1,%2,%3}, [%4];" \
                 : "=r"(r0), "=r"(r1), "=r"(r2), "=r"(r3) : "r"(addr))

#define MMA16816(c,a,b) \
    asm volatile("mma.sync.aligned.m16n8k16.row.col.f32.f16.f16.f32 " \
                 "{%0,%1,%2,%3}, {%4,%5,%6,%7}, {%8,%9}, {%0,%1,%2,%3};" \
                 : "+f"((c)[0]), "+f"((c)[1]), "+f"((c)[2]), "+f"((c)[3]) \
                 : "r"((a)[0]), "r"((a)[1]), "r"((a)[2]), "r"((a)[3]), \
                   "r"((b)[0]), "r"((b)[1]))

// ---------- kernel P1: zero flags + convert lA (transposed) and lB to fp16 ----------
__global__ void __launch_bounds__(256) prep_kernel(const float* __restrict__ lA,
                                                   const float* __restrict__ lB){
    const size_t TOT = (size_t)D_IN * K_LORA;   // 655360
    size_t gid = (size_t)blockIdx.x*256u + threadIdx.x;
    if (gid < 32) g_convCnt[gid] = 0;
    else if (gid < 48) g_foldCnt[gid-32] = 0;
    if (gid < TOT){
        int i = (int)(gid / K_LORA), k = (int)(gid % K_LORA);
        g_ahT[gid] = __float2half(lA[(size_t)k*D_IN + i]);   // lA [T,R,D_IN] flat
    } else if (gid < 2*TOT){
        size_t g = gid - TOT;
        int o = (int)(g / K_LORA), k = (int)(g % K_LORA);
        int t = k >> 4, r = k & 15;
        g_bh[g] = __float2half(lB[(size_t)t*D_OUT*RANK_ + (size_t)o*RANK_ + r]);
    }
}

// ---------- merged kernel ----------
// bid in [0,1024): producers, INTERLEAVED: even -> conv (idx=bid>>1), odd -> fold (idx=bid>>1)
// bid in [1024,2048): GEMM, n-fastest raster.
// GEMM: CTA tile 256(M) x 128(N), 16 warps (4x4), warp tile 64x32, K=4096 in 64-chunks,
//       4-stage cp.async ring, one __syncthreads per chunk, 144B padded rows.
// Fold: CTA tile 256(o) x 128(i), K=160 fp16 mma, 336B padded rows,
//       epilogue W_eff = fp16(W + acc/16) -> g_wh, then flag.
#define MT 256
#define NT 128
#define SROW 144
#define A_ST (MT*SROW)                 // 36864
#define B_ST (NT*SROW)                 // 18432
#define STG  (A_ST + B_ST)             // 55296
#define NSTAGE 4
#define GEMM_SMEM (NSTAGE*STG)         // 221184
#define NKI 64
#define FROW 336
#define FA_ST (256*FROW)               // 86016

__global__ void __launch_bounds__(512, 1)
fused_kernel(const float* __restrict__ W, const float* __restrict__ x,
             const float* __restrict__ bias, float* __restrict__ out){
    extern __shared__ char smem[];
    const uint32_t sbase = smem_u32(smem);
    const int bid = blockIdx.x;
    const int tid = threadIdx.x;
    const int wid = tid >> 5;
    const int l   = tid & 31;

    if (bid < 1024 && (bid & 1) == 0){
        // ---------------- x -> fp16 conversion: conv idx cb, rows [cb*16, cb*16+16) ----------------
        const int cb = bid >> 1;
        const size_t base = (size_t)cb * 16 * D_IN;
        const float4* src = reinterpret_cast<const float4*>(x + base);
#pragma unroll 4
        for (int it = 0; it < 32; it++){
            size_t i4 = (size_t)it*512 + tid;
            float4 v = src[i4];
            __half h[4];
            h[0]=__float2half(v.x); h[1]=__float2half(v.y);
            h[2]=__float2half(v.z); h[3]=__float2half(v.w);
            *reinterpret_cast<uint2*>(g_xh + base + i4*4) = *reinterpret_cast<uint2*>(h);
        }
        __threadfence();
        __syncthreads();
        if (tid == 0) atomicAdd(&g_convCnt[cb >> 4], 1);
        return;
    }

    if (bid < 1024){
        // ---------------- fold tile: idx fbid, o0 = ot*256, i0 = it*128, K=160 ----------------
        const int fbid = bid >> 1;
        const int ot = fbid >> 5;            // 0..15
        const int o0 = ot * 256;
        const int i0 = (fbid & 31) * 128;
        const uint32_t sa = sbase;           // Bh tile: 256 rows x 336B (320B valid)
        const uint32_t sb = sbase + FA_ST;   // AhT tile: 128 rows x 336B (320B valid)
        {
            // A-tile: 256 rows x 320B; 2 thr/row, each 160B = 10 x 16B chunks
            const int rA = tid >> 1, hA = tid & 1;
            const __half* gA = g_bh + (size_t)(o0 + rA)*K_LORA + hA*80;
            const uint32_t da = sa + (uint32_t)rA*FROW + (uint32_t)hA*160;
#pragma unroll
            for (int c=0;c<10;c++) cp16(da + c*16, gA + c*8);
            // B-tile: 128 rows x 320B; 4 thr/row, each 80B = 5 x 16B chunks
            const int rB = tid >> 2, qB = tid & 3;
            const __half* gB = g_ahT + (size_t)(i0 + rB)*K_LORA + qB*40;
            const uint32_t db = sb + (uint32_t)rB*FROW + (uint32_t)qB*80;
#pragma unroll
            for (int c=0;c<5;c++) cp16(db + c*16, gB + c*8);
        }
        asm volatile("cp.async.commit_group;\n\tcp.async.wait_group 0;" ::: "memory");
        __syncthreads();

        const int wm = wid & 3;     // o-group of 64
        const int wn = wid >> 2;    // i-group of 32
        float acc[4][4][4];
#pragma unroll
        for (int mi=0;mi<4;mi++)
#pragma unroll
            for (int nj=0;nj<4;nj++)
#pragma unroll
                for (int e=0;e<4;e++) acc[mi][nj][e] = 0.f;

        const uint32_t a_lane = (uint32_t)(wm*64 + (l & 15)) * FROW + (uint32_t)((l >> 4) & 1) * 16;
        const uint32_t b_lane = (uint32_t)(wn*32 + (l & 7) + ((l >> 4) & 1)*8) * FROW
                              + (uint32_t)((l >> 3) & 1) * 16;
#pragma unroll
        for (int ks = 0; ks < 10; ks++){
            uint32_t a[4][4];
#pragma unroll
            for (int mi=0;mi<4;mi++){
                uint32_t addr = sa + a_lane + (uint32_t)(mi*16)*FROW + (uint32_t)ks*32;
                LDSM4(a[mi][0], a[mi][1], a[mi][2], a[mi][3], addr);
            }
            uint32_t b[4][2];
#pragma unroll
            for (int nb=0;nb<2;nb++){
                uint32_t addr = sb + b_lane + (uint32_t)(nb*16)*FROW + (uint32_t)ks*32;
                LDSM4(b[2*nb][0], b[2*nb][1], b[2*nb+1][0], b[2*nb+1][1], addr);
            }
#pragma unroll
            for (int mi=0;mi<4;mi++)
#pragma unroll
                for (int nj=0;nj<4;nj++)
                    MMA16816(acc[mi][nj], a[mi], b[nj]);
        }

#pragma unroll
        for (int mi=0;mi<4;mi++){
            const int m = o0 + wm*64 + mi*16 + (l >> 2);
#pragma unroll
            for (int nj=0;nj<4;nj++){
                const int n = i0 + wn*32 + nj*8 + (l & 3)*2;
                float2 w01 = *reinterpret_cast<const float2*>(W + (size_t)m*D_IN + n);
                float2 w23 = *reinterpret_cast<const float2*>(W + (size_t)(m+8)*D_IN + n);
                __half2 h0 = __floats2half2_rn(w01.x + acc[mi][nj][0]*SCALING,
                                               w01.y + acc[mi][nj][1]*SCALING);
                __half2 h1 = __floats2half2_rn(w23.x + acc[mi][nj][2]*SCALING,
                                               w23.y + acc[mi][nj][3]*SCALING);
                *reinterpret_cast<__half2*>(g_wh + (size_t)m*D_IN + n)     = h0;
                *reinterpret_cast<__half2*>(g_wh + (size_t)(m+8)*D_IN + n) = h1;
            }
        }
        __threadfence();
        __syncthreads();
        if (tid == 0) atomicAdd(&g_foldCnt[ot], 1);
        return;
    }

    // ---------------- GEMM CTA: n-fastest raster (A-tile L2 reuse across n-group) ----------------
    const int gb  = bid - 1024;
    const int n_t = gb & 31;
    const int m_t = gb >> 5;
    const int m0  = m_t * MT;
    const int n0  = n_t * NT;

    // wait for producers (own tiles only)
    if (tid == 0){
        while (atomicAdd(&g_foldCnt[n_t >> 1], 0) < 32) { }
        while (atomicAdd(&g_convCnt[m_t], 0) < 16) { }
        __threadfence();
    }
    __syncthreads();

    const int wm  = wid & 3;    // 4 M-groups of 64
    const int wn  = wid >> 2;   // 4 N-groups of 32

    float acc[4][4][4];
#pragma unroll
    for (int mi=0;mi<4;mi++)
#pragma unroll
        for (int nj=0;nj<4;nj++)
#pragma unroll
            for (int e=0;e<4;e++) acc[mi][nj][e] = 0.f;

    const int arow = tid >> 1, ah = tid & 1;       // A: 256 rows, 2 thr/row, 4x16B
    const int brow = tid >> 2, bq = tid & 3;       // B: 128 rows, 4 thr/row, 2x16B

    auto issue_load = [&](int kk){
        const int k0  = kk << 6;
        const uint32_t as = sbase + (uint32_t)(kk % NSTAGE) * STG;
        const uint32_t bs = as + A_ST;
        const __half* ga = g_xh + (size_t)(m0 + arow)*D_IN + k0 + ah*32;
        const uint32_t adst = as + (uint32_t)arow*SROW + (uint32_t)ah*64;
#pragma unroll
        for (int c=0;c<4;c++) cp16(adst + c*16, ga + c*8);
        const __half* gbp = g_wh + (size_t)(n0 + brow)*D_IN + k0 + bq*16;
        const uint32_t bdst = bs + (uint32_t)brow*SROW + (uint32_t)bq*32;
#pragma unroll
        for (int c=0;c<2;c++) cp16(bdst + c*16, gbp + c*8);
        asm volatile("cp.async.commit_group;" ::: "memory");
    };

    issue_load(0);
    issue_load(1);
    issue_load(2);

    const uint32_t a_lane = (uint32_t)(wm*64 + (l & 15)) * SROW + (uint32_t)((l >> 4) & 1) * 16;
    const uint32_t b_lane = (uint32_t)(wn*32 + (l & 7) + ((l >> 4) & 1)*8) * SROW
                          + (uint32_t)((l >> 3) & 1) * 16;

    for (int kk = 0; kk < NKI; kk++){
        asm volatile("cp.async.wait_group 2;" ::: "memory");
        __syncthreads();

        if (kk + 3 < NKI) issue_load(kk + 3);
        else asm volatile("cp.async.commit_group;" ::: "memory");

        const uint32_t as = sbase + (uint32_t)(kk % NSTAGE) * STG;
        const uint32_t bs = as + A_ST;

#pragma unroll
        for (int ks = 0; ks < 4; ks++){
            uint32_t a[4][4];
#pragma unroll
            for (int mi=0;mi<4;mi++){
                uint32_t addr = as + a_lane + (uint32_t)(mi*16)*SROW + (uint32_t)ks*32;
                LDSM4(a[mi][0], a[mi][1], a[mi][2], a[mi][3], addr);
            }
            uint32_t b[4][2];
#pragma unroll
            for (int nb=0;nb<2;nb++){
                uint32_t addr = bs + b_lane + (uint32_t)(nb*16)*SROW + (uint32_t)ks*32;
                LDSM4(b[2*nb][0], b[2*nb][1], b[2*nb+1][0], b[2*nb+1][1], addr);
            }
#pragma unroll
            for (int mi=0;mi<4;mi++)
#pragma unroll
                for (int nj=0;nj<4;nj++)
                    MMA16816(acc[mi][nj], a[mi], b[nj]);
        }
    }

    // epilogue: add bias, store fp32
#pragma unroll
    for (int mi=0;mi<4;mi++){
        const int m = m0 + wm*64 + mi*16 + (l >> 2);
#pragma unroll
        for (int nj=0;nj<4;nj++){
            const int n = n0 + wn*32 + nj*8 + (l & 3)*2;
            const float b0 = bias[n], b1 = bias[n+1];
            float2 v0 = make_float2(acc[mi][nj][0] + b0, acc[mi][nj][1] + b1);
            float2 v1 = make_float2(acc[mi][nj][2] + b0, acc[mi][nj][3] + b1);
            *reinterpret_cast<float2*>(out + (size_t)m*D_OUT + n)       = v0;
            *reinterpret_cast<float2*>(out + (size_t)(m+8)*D_OUT + n)   = v1;
        }
    }
}

// ---------- launch ----------
extern "C" void kernel_launch(void* const* d_in, const int* in_sizes, int n_in,
                              void* d_out, int out_size){
    const float* x  = (const float*)d_in[0];
    const float* W  = (const float*)d_in[1];
    const float* b  = (const float*)d_in[2];
    const float* lA = (const float*)d_in[3];
    const float* lB = (const float*)d_in[4];
    float* out = (float*)d_out;

    cudaFuncSetAttribute(fused_kernel,
                         cudaFuncAttributeMaxDynamicSharedMemorySize, GEMM_SMEM);

    prep_kernel<<<(2*(size_t)D_IN*K_LORA + 255)/256, 256>>>(lA, lB);
    fused_kernel<<<2048, 512, GEMM_SMEM>>>(W, x, b, out);
}